// round 9
// baseline (speedup 1.0000x reference)
#include <cuda_runtime.h>
#include <cuda_fp16.h>
#include <cstdint>

#define NB 2
#define NN 8192
#define BM 64
#define NTILES 64
#define L2E 1.4426950408889634f

// -------- scratch (device globals; no allocation allowed) --------
__device__ __align__(16) __half g_Qh[NB][NN][16];  // fp16 Q, pre-scaled by log2e (A side)
__device__ __align__(16) __half g_Kh[NB][NN][16];  // fp16 K, unscaled (B side)
__device__ __align__(16) __half g_Vh[NB][NN][32];  // fp16 V
__device__ float g_Rn[NB][NN];                     // |Q_i|^2 (fp32, unscaled)
__device__ float g_bmax[NB][256];                  // per-block max |Q|^2 (no reset needed)

// ---------------- helpers ----------------
__device__ __forceinline__ uint32_t smem_u32(const void* p) {
    uint32_t a;
    asm("{ .reg .u64 t; cvta.to.shared.u64 t, %1; cvt.u32.u64 %0, t; }" : "=r"(a) : "l"(p));
    return a;
}
__device__ __forceinline__ void ldsm4(uint32_t* r, uint32_t a) {
    asm volatile("ldmatrix.sync.aligned.m8n8.x4.shared.b16 {%0,%1,%2,%3}, [%4];"
        : "=r"(r[0]), "=r"(r[1]), "=r"(r[2]), "=r"(r[3]) : "r"(a));
}
__device__ __forceinline__ void ldsm4t(uint32_t* r, uint32_t a) {
    asm volatile("ldmatrix.sync.aligned.m8n8.x4.trans.shared.b16 {%0,%1,%2,%3}, [%4];"
        : "=r"(r[0]), "=r"(r[1]), "=r"(r[2]), "=r"(r[3]) : "r"(a));
}
__device__ __forceinline__ void mma16816(float* d, const uint32_t* a, uint32_t b0, uint32_t b1) {
    asm volatile("mma.sync.aligned.m16n8k16.row.col.f32.f16.f16.f32 "
        "{%0,%1,%2,%3}, {%4,%5,%6,%7}, {%8,%9}, {%0,%1,%2,%3};"
        : "+f"(d[0]), "+f"(d[1]), "+f"(d[2]), "+f"(d[3])
        : "r"(a[0]), "r"(a[1]), "r"(a[2]), "r"(a[3]), "r"(b0), "r"(b1));
}
__device__ __forceinline__ uint32_t ex2p(float a, float b) {
    __half2 h = __floats2half2_rn(a, b);
    uint32_t x = *(uint32_t*)&h, r;
    asm("ex2.approx.f16x2 %0, %1;" : "=r"(r) : "r"(x));
    return r;
}
__device__ __forceinline__ void cp16(uint32_t dst, const void* src) {
    asm volatile("cp.async.ca.shared.global [%0], [%1], 16;" :: "r"(dst), "l"(src));
}
#define CP_COMMIT() asm volatile("cp.async.commit_group;" ::: "memory")
#define CP_WAIT1()  asm volatile("cp.async.wait_group 1;" ::: "memory")
#define CP_WAIT0()  asm volatile("cp.async.wait_group 0;" ::: "memory")

#define ONE2 0x3C003C00u   // half2 {1.0, 1.0}

// -------- kernel 1: Q (fp16, x log2e), K (fp16), V (fp16), norms, block max --------
__global__ void __launch_bounds__(128) qv_kernel(
    const float* __restrict__ inp, const float* __restrict__ W1,
    const float* __restrict__ b1,  const float* __restrict__ W2,
    const float* __restrict__ b2)
{
    __shared__ float Xs[32][32];
    __shared__ float W1s[16][32];
    __shared__ float W2s[32][32];
    __shared__ float b1s[16];
    __shared__ float b2s[32];
    __shared__ float Aq[32][16];

    int b  = blockIdx.x >> 8;
    int hw = blockIdx.x & 255;
    int tid = threadIdx.x;

    const float* ib = inp + (size_t)b * 262144 + hw * 32;
    for (int idx = tid; idx < 1024; idx += 128) {
        int l = idx >> 5, c = idx & 31;
        Xs[l][c] = ib[l * 8192 + c];
    }
    for (int idx = tid; idx < 512;  idx += 128) W1s[idx >> 5][idx & 31] = W1[idx];
    for (int idx = tid; idx < 1024; idx += 128) W2s[idx >> 5][idx & 31] = W2[idx];
    if (tid < 16) b1s[tid] = b1[tid];
    if (tid >= 32 && tid < 64) b2s[tid - 32] = b2[tid - 32];
    __syncthreads();

    for (int idx = tid; idx < 1024; idx += 128) {
        int o = idx >> 5, c = idx & 31;
        float s = b2s[o];
        #pragma unroll
        for (int l = 0; l < 32; l++) s += W2s[o][l] * Xs[l][c];
        g_Vh[b][o * 256 + hw][c] = __float2half(s);
    }
    for (int idx = tid; idx < 512; idx += 128) {
        int o = idx >> 5, ch = idx & 31;
        float s = b1s[o];
        #pragma unroll
        for (int l = 0; l < 32; l++) s += W1s[o][l] * Xs[l][ch];
        int k = ch >> 1, i12 = ch & 1;
        int row = i12 * 4096 + o * 256 + hw;
        g_Qh[b][row][k] = __float2half(s * L2E);
        g_Kh[b][row][k] = __float2half(s);
        Aq[(o << 1) | i12][k] = s;
    }
    __syncthreads();

    if (tid < 32) {
        int o = tid >> 1, i12 = tid & 1;
        float s = 0.f;
        #pragma unroll
        for (int k = 0; k < 16; k++) { float v = Aq[tid][k]; s += v * v; }
        g_Rn[b][i12 * 4096 + o * 256 + hw] = s;
        float m = s;
        #pragma unroll
        for (int off = 16; off; off >>= 1)
            m = fmaxf(m, __shfl_xor_sync(0xffffffffu, m, off));
        if (tid == 0) g_bmax[b][hw] = m;
    }
}

// ---- smem layout (one static arena, manually carved) ----
#define SQ_OFF   0            // Q: 2 KB
#define SK_OFF   2048         // K: 3 x 4 KB
#define SV_OFF   14336        // V: 3 x 8 KB
#define SRED_OFF 38912        // 8 floats
#define SM_BYTES 38944
// combine scratch overlays [0, 28416) after the mainloop

// -------- kernel 2: fp16 mma.sync attention; warps = 2 row-halves x 4 j-groups --------
// warp w: rows (w&1)*32..+32, j-cols (w>>1)*32..+32 of every 128-j tile.
// Fixed-shift softmax => the 4 j-groups' (D, l) partials add exactly at the end.
// 3 CTAs/SM target (regs capped at 85) to raise warps-in-flight per SMSP.
__global__ void __launch_bounds__(256, 3) attn7_kernel(
    const float* __restrict__ inp, const float* __restrict__ gamma,
    float* __restrict__ out)
{
    __shared__ __align__(16) char sm[SM_BYTES];

    int tid = threadIdx.x, lane = tid & 31, wid = tid >> 5;
    int rh = wid & 1, g = wid >> 1;
    int b = blockIdx.y;
    int i0 = blockIdx.x * BM;

    uint32_t sb = smem_u32(sm);
    float* red = (float*)(sm + SRED_OFF);

    // staging offsets (persistent across the whole kernel; hoisted out of the loop)
    const int kr = tid >> 1, ks = tid & 1;
    const uint32_t koff = kr * 32 + (ks ^ ((kr >> 2) & 1)) * 16;
    const int vr0 = tid >> 2, vs0 = tid & 3;
    const int e1 = tid + 256, vr1 = e1 >> 2, vs1 = e1 & 3;
    const uint32_t voff0 = vr0 * 64 + (vs0 ^ ((vr0 >> 1) & 3)) * 16;
    const uint32_t voff1 = vr1 * 64 + (vs1 ^ ((vr1 >> 1) & 3)) * 16;

    // ---- stage tiles 0/1 via cp.async; load Q; 256-way max reduce ----
    float mv = g_bmax[b][tid];
    {
        cp16(sb + SK_OFF + koff, &g_Kh[b][kr][ks * 8]);
        cp16(sb + SV_OFF + voff0, &g_Vh[b][vr0][vs0 * 8]);
        cp16(sb + SV_OFF + voff1, &g_Vh[b][vr1][vs1 * 8]);
        CP_COMMIT();
        cp16(sb + SK_OFF + 4096 + koff, &g_Kh[b][128 + kr][ks * 8]);
        cp16(sb + SV_OFF + 8192 + voff0, &g_Vh[b][128 + vr0][vs0 * 8]);
        cp16(sb + SV_OFF + 8192 + voff1, &g_Vh[b][128 + vr1][vs1 * 8]);
        CP_COMMIT();
    }
    if (tid < 128) {   // Q: 64 rows x 2 segs
        int r = tid >> 1, s = tid & 1;
        ((uint4*)(sm + SQ_OFF))[r * 2 + (s ^ ((r >> 2) & 1))] =
            *(const uint4*)&g_Qh[b][i0 + r][s * 8];
    }
    #pragma unroll
    for (int off = 16; off; off >>= 1)
        mv = fmaxf(mv, __shfl_xor_sync(0xffffffffu, mv, off));
    if (lane == 0) red[wid] = mv;
    __syncthreads();

    float msq = red[0];
    #pragma unroll
    for (int w = 1; w < 8; w++) msq = fmaxf(msq, red[w]);

    // ---- Q A-fragments: 2 per warp (rows rh*32 + fr*16) ----
    uint32_t qa[2][4];
    #pragma unroll
    for (int fr = 0; fr < 2; fr++) {
        int row = rh * 32 + fr * 16 + (lane & 7) + (lane & 8);
        int seg = lane >> 4;
        ldsm4(qa[fr], sb + SQ_OFF + row * 32 + (seg ^ ((row >> 2) & 1)) * 16);
    }

    float mh[2][2];
    #pragma unroll
    for (int fr = 0; fr < 2; fr++) {
        int ia = i0 + rh * 32 + fr * 16 + (lane >> 2);
        mh[fr][0] = L2E * sqrtf(g_Rn[b][ia] * msq);
        mh[fr][1] = L2E * sqrtf(g_Rn[b][ia + 8] * msq);
    }

    float Dc[2][16];
    float Dl[2][4];
    #pragma unroll
    for (int fr = 0; fr < 2; fr++) {
        #pragma unroll
        for (int q = 0; q < 16; q++) Dc[fr][q] = 0.f;
        #pragma unroll
        for (int q = 0; q < 4; q++) Dl[fr][q] = 0.f;
    }

    // ldsm offsets within a tile buffer (loop-invariant)
    uint32_t kfo, vfo0, vfo1;
    {
        int row = (g * 2) * 16 + (lane & 7) + ((lane >> 4) << 3);
        int seg = (lane >> 3) & 1;
        kfo = row * 32 + (seg ^ ((row >> 2) & 1)) * 16;
        int vrow = (g * 2) * 16 + (lane & 7) + (((lane >> 3) & 1) << 3);
        int vseg = (lane >> 4) & 1;
        vfo0 = vrow * 64 + ((vseg)     ^ ((vrow >> 1) & 3)) * 16;
        vfo1 = vrow * 64 + ((vseg + 2) ^ ((vrow >> 1) & 3)) * 16;
    }
    // np=1 offsets (row += 16): swizzle bits differ; compute both
    uint32_t kfo1, vfo0b, vfo1b;
    {
        int row = (g * 2 + 1) * 16 + (lane & 7) + ((lane >> 4) << 3);
        int seg = (lane >> 3) & 1;
        kfo1 = row * 32 + (seg ^ ((row >> 2) & 1)) * 16;
        int vrow = (g * 2 + 1) * 16 + (lane & 7) + (((lane >> 3) & 1) << 3);
        int vseg = (lane >> 4) & 1;
        vfo0b = vrow * 64 + ((vseg)     ^ ((vrow >> 1) & 3)) * 16;
        vfo1b = vrow * 64 + ((vseg + 2) ^ ((vrow >> 1) & 3)) * 16;
    }

    int cur = 0;   // buffer index of tile t
    for (int t = 0; t < NTILES; t++) {
        if (t < NTILES - 1) CP_WAIT1(); else CP_WAIT0();
        __syncthreads();

        // stage tile t+2 into the buffer freed at t-1
        if (t < NTILES - 2) {
            int nxt2 = cur + 2; if (nxt2 >= 3) nxt2 -= 3;
            int jb2 = (t + 2) * 128;
            cp16(sb + SK_OFF + nxt2 * 4096 + koff, &g_Kh[b][jb2 + kr][ks * 8]);
            cp16(sb + SV_OFF + nxt2 * 8192 + voff0, &g_Vh[b][jb2 + vr0][vs0 * 8]);
            cp16(sb + SV_OFF + nxt2 * 8192 + voff1, &g_Vh[b][jb2 + vr1][vs1 * 8]);
            CP_COMMIT();
        }

        uint32_t kb = sb + SK_OFF + cur * 4096;
        uint32_t vb = sb + SV_OFF + cur * 8192;

        // this warp's 2 strips of 16 j within its 32-col group
        #pragma unroll
        for (int np = 0; np < 2; np++) {
            uint32_t kf[4];
            ldsm4(kf, kb + (np ? kfo1 : kfo));
            uint32_t vf0[4], vf1[4];
            ldsm4t(vf0, vb + (np ? vfo0b : vfo0));
            ldsm4t(vf1, vb + (np ? vfo1b : vfo1));
            #pragma unroll
            for (int fr = 0; fr < 2; fr++) {
                float s0[4] = {-mh[fr][0], -mh[fr][0], -mh[fr][1], -mh[fr][1]};
                mma16816(s0, qa[fr], kf[0], kf[1]);
                float s1[4] = {-mh[fr][0], -mh[fr][0], -mh[fr][1], -mh[fr][1]};
                mma16816(s1, qa[fr], kf[2], kf[3]);

                uint32_t pA[4];
                pA[0] = ex2p(s0[0], s0[1]);
                pA[1] = ex2p(s0[2], s0[3]);
                pA[2] = ex2p(s1[0], s1[1]);
                pA[3] = ex2p(s1[2], s1[3]);

                mma16816(Dl[fr], pA, ONE2, ONE2);
                mma16816(Dc[fr] + 0,  pA, vf0[0], vf0[1]);
                mma16816(Dc[fr] + 4,  pA, vf0[2], vf0[3]);
                mma16816(Dc[fr] + 8,  pA, vf1[0], vf1[1]);
                mma16816(Dc[fr] + 12, pA, vf1[2], vf1[3]);
            }
        }
        cur++; if (cur == 3) cur = 0;
    }

    // ---- combine the 4 j-groups' partials (scratch overlays K/V region) ----
    __syncthreads();   // everyone done reading tile buffers
    float* scr = (float*)sm;
    if (g > 0) {
        float* p = scr + (((g - 1) * 2 + rh) * 32 + lane) * 37;
        #pragma unroll
        for (int fr = 0; fr < 2; fr++) {
            #pragma unroll
            for (int q = 0; q < 16; q++) p[fr * 16 + q] = Dc[fr][q];
        }
        p[32] = Dl[0][0]; p[33] = Dl[0][2];
        p[34] = Dl[1][0]; p[35] = Dl[1][2];
    }
    __syncthreads();

    if (g == 0) {
        float la[2], lb[2];
        la[0] = Dl[0][0]; lb[0] = Dl[0][2];
        la[1] = Dl[1][0]; lb[1] = Dl[1][2];
        #pragma unroll
        for (int gg = 0; gg < 3; gg++) {
            const float* p = scr + ((gg * 2 + rh) * 32 + lane) * 37;
            #pragma unroll
            for (int fr = 0; fr < 2; fr++) {
                #pragma unroll
                for (int q = 0; q < 16; q++) Dc[fr][q] += p[fr * 16 + q];
            }
            la[0] += p[32]; lb[0] += p[33];
            la[1] += p[34]; lb[1] += p[35];
        }

        float gm = gamma[0];
        #pragma unroll
        for (int fr = 0; fr < 2; fr++) {
            float ra = gm / la[fr], rb = gm / lb[fr];
            int ia = i0 + rh * 32 + fr * 16 + (lane >> 2);
            size_t ba = (size_t)b * 262144 + (size_t)ia * 32;
            size_t bb = ba + 8 * 32;
            #pragma unroll
            for (int nt = 0; nt < 4; nt++) {
                int col = nt * 8 + (lane & 3) * 2;
                float2 iv = *(const float2*)(inp + ba + col);
                float2 ov;
                ov.x = Dc[fr][nt * 4 + 0] * ra + iv.x;
                ov.y = Dc[fr][nt * 4 + 1] * ra + iv.y;
                *(float2*)(out + ba + col) = ov;
                iv = *(const float2*)(inp + bb + col);
                ov.x = Dc[fr][nt * 4 + 2] * rb + iv.x;
                ov.y = Dc[fr][nt * 4 + 3] * rb + iv.y;
                *(float2*)(out + bb + col) = ov;
            }
        }
    }
}

extern "C" void kernel_launch(void* const* d_in, const int* in_sizes, int n_in,
                              void* d_out, int out_size) {
    const float* inp   = (const float*)d_in[0];
    const float* W1    = (const float*)d_in[1];
    const float* b1    = (const float*)d_in[2];
    const float* W2    = (const float*)d_in[3];
    const float* b2    = (const float*)d_in[4];
    const float* gamma = (const float*)d_in[5];
    float* out = (float*)d_out;

    qv_kernel<<<NB * 256, 128>>>(inp, W1, b1, W2, b2);
    attn7_kernel<<<dim3(NN / BM, NB), 256>>>(inp, gamma, out);
}

// round 10
// speedup vs baseline: 1.0945x; 1.0945x over previous
#include <cuda_runtime.h>
#include <cuda_fp16.h>
#include <cstdint>

#define NB 2
#define NN 8192
#define BM 32
#define NTILES 64
#define L2E 1.4426950408889634f

// -------- scratch (device globals; no allocation allowed) --------
__device__ __align__(16) __half g_Qh[NB][NN][16];  // fp16 Q, pre-scaled by log2e (A side)
__device__ __align__(16) __half g_Kh[NB][NN][16];  // fp16 K, unscaled (B side)
__device__ __align__(16) __half g_Vh[NB][NN][32];  // fp16 V
__device__ float g_Rn[NB][NN];                     // |Q_i|^2 (fp32, unscaled)
__device__ float g_bmax[NB][256];                  // per-block max |Q|^2 (no reset needed)

// ---------------- helpers ----------------
__device__ __forceinline__ uint32_t smem_u32(const void* p) {
    uint32_t a;
    asm("{ .reg .u64 t; cvta.to.shared.u64 t, %1; cvt.u32.u64 %0, t; }" : "=r"(a) : "l"(p));
    return a;
}
__device__ __forceinline__ void ldsm4(uint32_t* r, uint32_t a) {
    asm volatile("ldmatrix.sync.aligned.m8n8.x4.shared.b16 {%0,%1,%2,%3}, [%4];"
        : "=r"(r[0]), "=r"(r[1]), "=r"(r[2]), "=r"(r[3]) : "r"(a));
}
__device__ __forceinline__ void ldsm4t(uint32_t* r, uint32_t a) {
    asm volatile("ldmatrix.sync.aligned.m8n8.x4.trans.shared.b16 {%0,%1,%2,%3}, [%4];"
        : "=r"(r[0]), "=r"(r[1]), "=r"(r[2]), "=r"(r[3]) : "r"(a));
}
__device__ __forceinline__ void mma16816(float* d, const uint32_t* a, uint32_t b0, uint32_t b1) {
    asm volatile("mma.sync.aligned.m16n8k16.row.col.f32.f16.f16.f32 "
        "{%0,%1,%2,%3}, {%4,%5,%6,%7}, {%8,%9}, {%0,%1,%2,%3};"
        : "+f"(d[0]), "+f"(d[1]), "+f"(d[2]), "+f"(d[3])
        : "r"(a[0]), "r"(a[1]), "r"(a[2]), "r"(a[3]), "r"(b0), "r"(b1));
}
__device__ __forceinline__ uint32_t ex2p(float a, float b) {
    __half2 h = __floats2half2_rn(a, b);
    uint32_t x = *(uint32_t*)&h, r;
    asm("ex2.approx.f16x2 %0, %1;" : "=r"(r) : "r"(x));
    return r;
}
__device__ __forceinline__ void cp16(uint32_t dst, const void* src) {
    asm volatile("cp.async.ca.shared.global [%0], [%1], 16;" :: "r"(dst), "l"(src));
}
#define CP_COMMIT() asm volatile("cp.async.commit_group;" ::: "memory")
#define CP_WAIT1()  asm volatile("cp.async.wait_group 1;" ::: "memory")
#define CP_WAIT0()  asm volatile("cp.async.wait_group 0;" ::: "memory")

#define ONE2 0x3C003C00u   // half2 {1.0, 1.0}

// -------- kernel 1: Q (fp16, x log2e), K (fp16), V (fp16), norms, block max --------
__global__ void __launch_bounds__(128) qv_kernel(
    const float* __restrict__ inp, const float* __restrict__ W1,
    const float* __restrict__ b1,  const float* __restrict__ W2,
    const float* __restrict__ b2)
{
    __shared__ float Xs[32][32];
    __shared__ float W1s[16][32];
    __shared__ float W2s[32][32];
    __shared__ float b1s[16];
    __shared__ float b2s[32];
    __shared__ float Aq[32][16];

    int b  = blockIdx.x >> 8;
    int hw = blockIdx.x & 255;
    int tid = threadIdx.x;

    const float* ib = inp + (size_t)b * 262144 + hw * 32;
    for (int idx = tid; idx < 1024; idx += 128) {
        int l = idx >> 5, c = idx & 31;
        Xs[l][c] = ib[l * 8192 + c];
    }
    for (int idx = tid; idx < 512;  idx += 128) W1s[idx >> 5][idx & 31] = W1[idx];
    for (int idx = tid; idx < 1024; idx += 128) W2s[idx >> 5][idx & 31] = W2[idx];
    if (tid < 16) b1s[tid] = b1[tid];
    if (tid >= 32 && tid < 64) b2s[tid - 32] = b2[tid - 32];
    __syncthreads();

    for (int idx = tid; idx < 1024; idx += 128) {
        int o = idx >> 5, c = idx & 31;
        float s = b2s[o];
        #pragma unroll
        for (int l = 0; l < 32; l++) s += W2s[o][l] * Xs[l][c];
        g_Vh[b][o * 256 + hw][c] = __float2half(s);
    }
    for (int idx = tid; idx < 512; idx += 128) {
        int o = idx >> 5, ch = idx & 31;
        float s = b1s[o];
        #pragma unroll
        for (int l = 0; l < 32; l++) s += W1s[o][l] * Xs[l][ch];
        int k = ch >> 1, i12 = ch & 1;
        int row = i12 * 4096 + o * 256 + hw;
        g_Qh[b][row][k] = __float2half(s * L2E);
        g_Kh[b][row][k] = __float2half(s);
        Aq[(o << 1) | i12][k] = s;
    }
    __syncthreads();

    if (tid < 32) {
        int o = tid >> 1, i12 = tid & 1;
        float s = 0.f;
        #pragma unroll
        for (int k = 0; k < 16; k++) { float v = Aq[tid][k]; s += v * v; }
        g_Rn[b][i12 * 4096 + o * 256 + hw] = s;
        float m = s;
        #pragma unroll
        for (int off = 16; off; off >>= 1)
            m = fmaxf(m, __shfl_xor_sync(0xffffffffu, m, off));
        if (tid == 0) g_bmax[b][hw] = m;
    }
}

// ---- smem layout (one static arena, manually carved) ----
#define SQ_OFF   0            // Q: 1 KB (32 rows)
#define SK_OFF   1024         // K: 3 x 4 KB
#define SV_OFF   13312        // V: 3 x 8 KB
#define SRED_OFF 37888        // 8 floats
#define SM_BYTES 37920
// combine scratch overlays [0, ~14.6KB) after the mainloop

// -------- kernel 2: fp16 mma.sync attention; warps = 2 row-halves(16) x 4 j-groups --------
// warp w: rows (w&1)*16..+16, j-cols (w>>1)*32..+32 of every 128-j tile.
// Fixed-shift softmax => the 4 j-groups' (D, l) partials add exactly at the end.
// Small per-warp state (1 row fragment) so 3 CTAs/SM fit WITHOUT spilling.
__global__ void __launch_bounds__(256, 3) attn8_kernel(
    const float* __restrict__ inp, const float* __restrict__ gamma,
    float* __restrict__ out)
{
    __shared__ __align__(16) char sm[SM_BYTES];

    int tid = threadIdx.x, lane = tid & 31, wid = tid >> 5;
    int rh = wid & 1, g = wid >> 1;
    int b = blockIdx.y;
    int i0 = blockIdx.x * BM;

    uint32_t sb = smem_u32(sm);
    float* red = (float*)(sm + SRED_OFF);

    // staging offsets (persistent; hoisted)
    const int kr = tid >> 1, ks = tid & 1;
    const uint32_t koff = kr * 32 + (ks ^ ((kr >> 2) & 1)) * 16;
    const int vr0 = tid >> 2, vs0 = tid & 3;
    const int e1 = tid + 256, vr1 = e1 >> 2, vs1 = e1 & 3;
    const uint32_t voff0 = vr0 * 64 + (vs0 ^ ((vr0 >> 1) & 3)) * 16;
    const uint32_t voff1 = vr1 * 64 + (vs1 ^ ((vr1 >> 1) & 3)) * 16;

    // ---- stage tiles 0/1 via cp.async; load Q; 256-way max reduce ----
    float mv = g_bmax[b][tid];
    {
        cp16(sb + SK_OFF + koff, &g_Kh[b][kr][ks * 8]);
        cp16(sb + SV_OFF + voff0, &g_Vh[b][vr0][vs0 * 8]);
        cp16(sb + SV_OFF + voff1, &g_Vh[b][vr1][vs1 * 8]);
        CP_COMMIT();
        cp16(sb + SK_OFF + 4096 + koff, &g_Kh[b][128 + kr][ks * 8]);
        cp16(sb + SV_OFF + 8192 + voff0, &g_Vh[b][128 + vr0][vs0 * 8]);
        cp16(sb + SV_OFF + 8192 + voff1, &g_Vh[b][128 + vr1][vs1 * 8]);
        CP_COMMIT();
    }
    if (tid < 64) {   // Q: 32 rows x 2 segs
        int r = tid >> 1, s = tid & 1;
        ((uint4*)(sm + SQ_OFF))[r * 2 + (s ^ ((r >> 2) & 1))] =
            *(const uint4*)&g_Qh[b][i0 + r][s * 8];
    }
    #pragma unroll
    for (int off = 16; off; off >>= 1)
        mv = fmaxf(mv, __shfl_xor_sync(0xffffffffu, mv, off));
    if (lane == 0) red[wid] = mv;
    __syncthreads();

    float msq = red[0];
    #pragma unroll
    for (int w = 1; w < 8; w++) msq = fmaxf(msq, red[w]);

    // ---- Q A-fragment (one 16-row strip per warp) ----
    uint32_t qa[4];
    {
        int row = rh * 16 + (lane & 7) + (lane & 8);
        int seg = lane >> 4;
        ldsm4(qa, sb + SQ_OFF + row * 32 + (seg ^ ((row >> 2) & 1)) * 16);
    }

    float mh0, mh1;
    {
        int ia = i0 + rh * 16 + (lane >> 2);
        mh0 = L2E * sqrtf(g_Rn[b][ia] * msq);
        mh1 = L2E * sqrtf(g_Rn[b][ia + 8] * msq);
    }

    float Dc[16];
    float Dl[4];
    #pragma unroll
    for (int q = 0; q < 16; q++) Dc[q] = 0.f;
    #pragma unroll
    for (int q = 0; q < 4; q++) Dl[q] = 0.f;

    // ldsm offsets within a tile buffer (loop-invariant; np=0/1 differ in swizzle)
    uint32_t kfo0, kfo1, vfo00, vfo01, vfo10, vfo11;
    {
        int row = (g * 2) * 16 + (lane & 7) + ((lane >> 4) << 3);
        int seg = (lane >> 3) & 1;
        kfo0 = row * 32 + (seg ^ ((row >> 2) & 1)) * 16;
        int vrow = (g * 2) * 16 + (lane & 7) + (((lane >> 3) & 1) << 3);
        int vseg = (lane >> 4) & 1;
        vfo00 = vrow * 64 + ((vseg)     ^ ((vrow >> 1) & 3)) * 16;
        vfo01 = vrow * 64 + ((vseg + 2) ^ ((vrow >> 1) & 3)) * 16;
    }
    {
        int row = (g * 2 + 1) * 16 + (lane & 7) + ((lane >> 4) << 3);
        int seg = (lane >> 3) & 1;
        kfo1 = row * 32 + (seg ^ ((row >> 2) & 1)) * 16;
        int vrow = (g * 2 + 1) * 16 + (lane & 7) + (((lane >> 3) & 1) << 3);
        int vseg = (lane >> 4) & 1;
        vfo10 = vrow * 64 + ((vseg)     ^ ((vrow >> 1) & 3)) * 16;
        vfo11 = vrow * 64 + ((vseg + 2) ^ ((vrow >> 1) & 3)) * 16;
    }

    int cur = 0;   // buffer index of tile t
    for (int t = 0; t < NTILES; t++) {
        if (t < NTILES - 1) CP_WAIT1(); else CP_WAIT0();
        __syncthreads();

        // stage tile t+2 into the buffer freed at t-1
        if (t < NTILES - 2) {
            int nxt2 = cur + 2; if (nxt2 >= 3) nxt2 -= 3;
            int jb2 = (t + 2) * 128;
            cp16(sb + SK_OFF + nxt2 * 4096 + koff, &g_Kh[b][jb2 + kr][ks * 8]);
            cp16(sb + SV_OFF + nxt2 * 8192 + voff0, &g_Vh[b][jb2 + vr0][vs0 * 8]);
            cp16(sb + SV_OFF + nxt2 * 8192 + voff1, &g_Vh[b][jb2 + vr1][vs1 * 8]);
            CP_COMMIT();
        }

        uint32_t kb = sb + SK_OFF + cur * 4096;
        uint32_t vb = sb + SV_OFF + cur * 8192;

        // this warp's 2 strips of 16 j within its 32-col group
        #pragma unroll
        for (int np = 0; np < 2; np++) {
            uint32_t kf[4];
            ldsm4(kf, kb + (np ? kfo1 : kfo0));
            uint32_t vf0[4], vf1[4];
            ldsm4t(vf0, vb + (np ? vfo10 : vfo00));
            ldsm4t(vf1, vb + (np ? vfo11 : vfo01));

            float s0[4] = {-mh0, -mh0, -mh1, -mh1};
            mma16816(s0, qa, kf[0], kf[1]);
            float s1[4] = {-mh0, -mh0, -mh1, -mh1};
            mma16816(s1, qa, kf[2], kf[3]);

            uint32_t pA[4];
            pA[0] = ex2p(s0[0], s0[1]);
            pA[1] = ex2p(s0[2], s0[3]);
            pA[2] = ex2p(s1[0], s1[1]);
            pA[3] = ex2p(s1[2], s1[3]);

            mma16816(Dl, pA, ONE2, ONE2);
            mma16816(Dc + 0,  pA, vf0[0], vf0[1]);
            mma16816(Dc + 4,  pA, vf0[2], vf0[3]);
            mma16816(Dc + 8,  pA, vf1[0], vf1[1]);
            mma16816(Dc + 12, pA, vf1[2], vf1[3]);
        }
        cur++; if (cur == 3) cur = 0;
    }

    // ---- combine the 4 j-groups' partials (scratch overlays Q/K region) ----
    __syncthreads();   // everyone done reading tile buffers
    float* scr = (float*)sm;
    if (g > 0) {
        float* p = scr + (((g - 1) * 2 + rh) * 32 + lane) * 19;
        #pragma unroll
        for (int q = 0; q < 16; q++) p[q] = Dc[q];
        p[16] = Dl[0];
        p[17] = Dl[2];
    }
    __syncthreads();

    if (g == 0) {
        float la = Dl[0], lb = Dl[2];
        #pragma unroll
        for (int gg = 0; gg < 3; gg++) {
            const float* p = scr + ((gg * 2 + rh) * 32 + lane) * 19;
            #pragma unroll
            for (int q = 0; q < 16; q++) Dc[q] += p[q];
            la += p[16];
            lb += p[17];
        }

        float gm = gamma[0];
        float ra = gm / la, rb = gm / lb;
        int ia = i0 + rh * 16 + (lane >> 2);
        size_t ba = (size_t)b * 262144 + (size_t)ia * 32;
        size_t bb = ba + 8 * 32;
        #pragma unroll
        for (int nt = 0; nt < 4; nt++) {
            int col = nt * 8 + (lane & 3) * 2;
            float2 iv = *(const float2*)(inp + ba + col);
            float2 ov;
            ov.x = Dc[nt * 4 + 0] * ra + iv.x;
            ov.y = Dc[nt * 4 + 1] * ra + iv.y;
            *(float2*)(out + ba + col) = ov;
            iv = *(const float2*)(inp + bb + col);
            ov.x = Dc[nt * 4 + 2] * rb + iv.x;
            ov.y = Dc[nt * 4 + 3] * rb + iv.y;
            *(float2*)(out + bb + col) = ov;
        }
    }
}

extern "C" void kernel_launch(void* const* d_in, const int* in_sizes, int n_in,
                              void* d_out, int out_size) {
    const float* inp   = (const float*)d_in[0];
    const float* W1    = (const float*)d_in[1];
    const float* b1    = (const float*)d_in[2];
    const float* W2    = (const float*)d_in[3];
    const float* b2    = (const float*)d_in[4];
    const float* gamma = (const float*)d_in[5];
    float* out = (float*)d_out;

    qv_kernel<<<NB * 256, 128>>>(inp, W1, b1, W2, b2);
    attn8_kernel<<<dim3(NN / BM, NB), 256>>>(inp, gamma, out);
}

// round 11
// speedup vs baseline: 1.3433x; 1.2274x over previous
#include <cuda_runtime.h>
#include <cuda_fp16.h>
#include <cstdint>

#define NB 2
#define NN 8192
#define BM 64
#define NTILES 64
#define L2E 1.4426950408889634f

// -------- scratch (device globals; no allocation allowed) --------
__device__ __align__(16) __half g_Qh[NB][NN][16];  // fp16 Q, pre-scaled by log2e (A side)
__device__ __align__(16) __half g_Kh[NB][NN][16];  // fp16 K, unscaled (B side)
__device__ __align__(16) __half g_Vh[NB][NN][32];  // fp16 V
__device__ float g_Rn[NB][NN];                     // |Q_i|^2 (fp32, unscaled)
__device__ float g_bmax[NB][256];                  // per-block max |Q|^2
__device__ unsigned g_barrier;                     // grid barrier epoch counter (monotonic)

// ---------------- helpers ----------------
__device__ __forceinline__ uint32_t smem_u32(const void* p) {
    uint32_t a;
    asm("{ .reg .u64 t; cvta.to.shared.u64 t, %1; cvt.u32.u64 %0, t; }" : "=r"(a) : "l"(p));
    return a;
}
__device__ __forceinline__ void ldsm4(uint32_t* r, uint32_t a) {
    asm volatile("ldmatrix.sync.aligned.m8n8.x4.shared.b16 {%0,%1,%2,%3}, [%4];"
        : "=r"(r[0]), "=r"(r[1]), "=r"(r[2]), "=r"(r[3]) : "r"(a));
}
__device__ __forceinline__ void ldsm4t(uint32_t* r, uint32_t a) {
    asm volatile("ldmatrix.sync.aligned.m8n8.x4.trans.shared.b16 {%0,%1,%2,%3}, [%4];"
        : "=r"(r[0]), "=r"(r[1]), "=r"(r[2]), "=r"(r[3]) : "r"(a));
}
// f32-accumulate MMA (PV, row-sum)
__device__ __forceinline__ void mma16816(float* d, const uint32_t* a, uint32_t b0, uint32_t b1) {
    asm volatile("mma.sync.aligned.m16n8k16.row.col.f32.f16.f16.f32 "
        "{%0,%1,%2,%3}, {%4,%5,%6,%7}, {%8,%9}, {%0,%1,%2,%3};"
        : "+f"(d[0]), "+f"(d[1]), "+f"(d[2]), "+f"(d[3])
        : "r"(a[0]), "r"(a[1]), "r"(a[2]), "r"(a[3]), "r"(b0), "r"(b1));
}
// f16-accumulate MMA (S) — D layout == PV A-fragment layout
__device__ __forceinline__ void mma16816h(uint32_t* d, const uint32_t* a, uint32_t b0, uint32_t b1,
                                          uint32_t c0, uint32_t c1) {
    asm volatile("mma.sync.aligned.m16n8k16.row.col.f16.f16.f16.f16 "
        "{%0,%1}, {%2,%3,%4,%5}, {%6,%7}, {%8,%9};"
        : "=r"(d[0]), "=r"(d[1])
        : "r"(a[0]), "r"(a[1]), "r"(a[2]), "r"(a[3]), "r"(b0), "r"(b1), "r"(c0), "r"(c1));
}
__device__ __forceinline__ uint32_t ex2h(uint32_t x) {
    uint32_t r; asm("ex2.approx.f16x2 %0, %1;" : "=r"(r) : "r"(x)); return r;
}
__device__ __forceinline__ uint32_t packh2(float a, float b) {
    __half2 h = __floats2half2_rn(a, b);
    return *(uint32_t*)&h;
}
__device__ __forceinline__ void cp16(uint32_t dst, const void* src) {
    asm volatile("cp.async.ca.shared.global [%0], [%1], 16;" :: "r"(dst), "l"(src));
}
#define CP_COMMIT() asm volatile("cp.async.commit_group;" ::: "memory")
#define CP_WAIT1()  asm volatile("cp.async.wait_group 1;" ::: "memory")
#define CP_WAIT0()  asm volatile("cp.async.wait_group 0;" ::: "memory")

#define ONE2 0x3C003C00u   // half2 {1.0, 1.0}

// ---- smem arena (attn phase layout; qv phase overlays the front) ----
#define SQ_OFF   0            // Q: 2 KB
#define SK_OFF   2048         // K: 3 x 4 KB
#define SV_OFF   14336        // V: 3 x 8 KB
#define SRED_OFF 38912        // 8 floats
#define SM_BYTES 38944
// qv overlay: Xs@0(4K) W1s@4096(2K) W2s@6144(4K) b1s@10240 b2s@10304 Aq@10432(2K)

// ======== fused kernel: qv phase -> grid barrier -> attn phase ========
// Grid MUST be 256 CTAs with >=2 CTAs/SM residency (148*2=296>256) for the spin barrier.
__global__ void __launch_bounds__(256, 2) fused_kernel(
    const float* __restrict__ inp, const float* __restrict__ W1,
    const float* __restrict__ b1,  const float* __restrict__ W2,
    const float* __restrict__ b2,  const float* __restrict__ gamma,
    float* __restrict__ out)
{
    __shared__ __align__(16) char sm[SM_BYTES];

    int tid = threadIdx.x, lane = tid & 31, wid = tid >> 5;
    int flat = blockIdx.x + (int)gridDim.x * blockIdx.y;   // 0..255

    // ================= qv phase: this CTA computes 2 (b,hw) columns =================
    {
        float (*Xs)[32]  = (float(*)[32])(sm + 0);
        float (*W1s)[32] = (float(*)[32])(sm + 4096);
        float (*W2s)[32] = (float(*)[32])(sm + 6144);
        float* b1s = (float*)(sm + 10240);
        float* b2s = (float*)(sm + 10304);
        float (*Aq)[16]  = (float(*)[16])(sm + 10432);

        for (int idx = tid; idx < 512;  idx += 256) W1s[idx >> 5][idx & 31] = W1[idx];
        for (int idx = tid; idx < 1024; idx += 256) W2s[idx >> 5][idx & 31] = W2[idx];
        if (tid < 16) b1s[tid] = b1[tid];
        if (tid >= 32 && tid < 64) b2s[tid - 32] = b2[tid - 32];

        #pragma unroll 1
        for (int p = 0; p < 2; p++) {
            int q = flat * 2 + p;
            int b = q >> 8, hw = q & 255;
            __syncthreads();
            const float* ib = inp + (size_t)b * 262144 + hw * 32;
            for (int idx = tid; idx < 1024; idx += 256) {
                int l = idx >> 5, c = idx & 31;
                Xs[l][c] = ib[l * 8192 + c];
            }
            __syncthreads();

            for (int idx = tid; idx < 1024; idx += 256) {
                int o = idx >> 5, c = idx & 31;
                float s = b2s[o];
                #pragma unroll
                for (int l = 0; l < 32; l++) s += W2s[o][l] * Xs[l][c];
                g_Vh[b][o * 256 + hw][c] = __float2half(s);
            }
            for (int idx = tid; idx < 512; idx += 256) {
                int o = idx >> 5, ch = idx & 31;
                float s = b1s[o];
                #pragma unroll
                for (int l = 0; l < 32; l++) s += W1s[o][l] * Xs[l][ch];
                int k = ch >> 1, i12 = ch & 1;
                int row = i12 * 4096 + o * 256 + hw;
                g_Qh[b][row][k] = __float2half(s * L2E);
                g_Kh[b][row][k] = __float2half(s);
                Aq[(o << 1) | i12][k] = s;
            }
            __syncthreads();

            if (tid < 32) {
                int o = tid >> 1, i12 = tid & 1;
                float s = 0.f;
                #pragma unroll
                for (int k = 0; k < 16; k++) { float v = Aq[tid][k]; s += v * v; }
                g_Rn[b][i12 * 4096 + o * 256 + hw] = s;
                float m = s;
                #pragma unroll
                for (int off = 16; off; off >>= 1)
                    m = fmaxf(m, __shfl_xor_sync(0xffffffffu, m, off));
                if (tid == 0) g_bmax[b][hw] = m;
            }
        }
    }

    // ================= grid-wide barrier (epoch counter; launches are serialized) ====
    __threadfence();
    __syncthreads();
    if (tid == 0) {
        unsigned old = atomicAdd(&g_barrier, 1u);
        unsigned target = ((old >> 8) + 1u) << 8;   // this launch's completion value
        for (;;) {
            unsigned v;
            asm volatile("ld.volatile.global.u32 %0, [%1];" : "=r"(v) : "l"(&g_barrier));
            if (v >= target) break;
            __nanosleep(64);
        }
    }
    __syncthreads();

    // ================= attn phase (R8 structure; S-MMA in f16 accumulate) ============
    int rh = wid & 1, g = wid >> 1;
    int b = blockIdx.y;
    int i0 = blockIdx.x * BM;

    uint32_t sb = smem_u32(sm);
    float* red = (float*)(sm + SRED_OFF);

    const int kr = tid >> 1, ks = tid & 1;
    const uint32_t koff = kr * 32 + (ks ^ ((kr >> 2) & 1)) * 16;
    const int vr0 = tid >> 2, vs0 = tid & 3;
    const int e1 = tid + 256, vr1 = e1 >> 2, vs1 = e1 & 3;
    const uint32_t voff0 = vr0 * 64 + (vs0 ^ ((vr0 >> 1) & 3)) * 16;
    const uint32_t voff1 = vr1 * 64 + (vs1 ^ ((vr1 >> 1) & 3)) * 16;

    float mv = g_bmax[b][tid];
    {
        cp16(sb + SK_OFF + koff, &g_Kh[b][kr][ks * 8]);
        cp16(sb + SV_OFF + voff0, &g_Vh[b][vr0][vs0 * 8]);
        cp16(sb + SV_OFF + voff1, &g_Vh[b][vr1][vs1 * 8]);
        CP_COMMIT();
        cp16(sb + SK_OFF + 4096 + koff, &g_Kh[b][128 + kr][ks * 8]);
        cp16(sb + SV_OFF + 8192 + voff0, &g_Vh[b][128 + vr0][vs0 * 8]);
        cp16(sb + SV_OFF + 8192 + voff1, &g_Vh[b][128 + vr1][vs1 * 8]);
        CP_COMMIT();
    }
    if (tid < 128) {   // Q: 64 rows x 2 segs
        int r = tid >> 1, s = tid & 1;
        ((uint4*)(sm + SQ_OFF))[r * 2 + (s ^ ((r >> 2) & 1))] =
            *(const uint4*)&g_Qh[b][i0 + r][s * 8];
    }
    #pragma unroll
    for (int off = 16; off; off >>= 1)
        mv = fmaxf(mv, __shfl_xor_sync(0xffffffffu, mv, off));
    if (lane == 0) red[wid] = mv;
    __syncthreads();

    float msq = red[0];
    #pragma unroll
    for (int w = 1; w < 8; w++) msq = fmaxf(msq, red[w]);

    uint32_t qa[2][4];
    #pragma unroll
    for (int fr = 0; fr < 2; fr++) {
        int row = rh * 32 + fr * 16 + (lane & 7) + (lane & 8);
        int seg = lane >> 4;
        ldsm4(qa[fr], sb + SQ_OFF + row * 32 + (seg ^ ((row >> 2) & 1)) * 16);
    }

    uint32_t mch[2][2];   // packed half2 {-mh,-mh} for rows r / r+8
    #pragma unroll
    for (int fr = 0; fr < 2; fr++) {
        int ia = i0 + rh * 32 + fr * 16 + (lane >> 2);
        float m0 = L2E * sqrtf(g_Rn[b][ia] * msq);
        float m1 = L2E * sqrtf(g_Rn[b][ia + 8] * msq);
        mch[fr][0] = packh2(-m0, -m0);
        mch[fr][1] = packh2(-m1, -m1);
    }

    float Dc[2][16];
    float Dl[2][4];
    #pragma unroll
    for (int fr = 0; fr < 2; fr++) {
        #pragma unroll
        for (int q = 0; q < 16; q++) Dc[fr][q] = 0.f;
        #pragma unroll
        for (int q = 0; q < 4; q++) Dl[fr][q] = 0.f;
    }

    // ldsm offsets (loop-invariant)
    uint32_t kfo0, kfo1, vfo00, vfo01, vfo10, vfo11;
    {
        int row = (g * 2) * 16 + (lane & 7) + ((lane >> 4) << 3);
        int seg = (lane >> 3) & 1;
        kfo0 = row * 32 + (seg ^ ((row >> 2) & 1)) * 16;
        int vrow = (g * 2) * 16 + (lane & 7) + (((lane >> 3) & 1) << 3);
        int vseg = (lane >> 4) & 1;
        vfo00 = vrow * 64 + ((vseg)     ^ ((vrow >> 1) & 3)) * 16;
        vfo01 = vrow * 64 + ((vseg + 2) ^ ((vrow >> 1) & 3)) * 16;
    }
    {
        int row = (g * 2 + 1) * 16 + (lane & 7) + ((lane >> 4) << 3);
        int seg = (lane >> 3) & 1;
        kfo1 = row * 32 + (seg ^ ((row >> 2) & 1)) * 16;
        int vrow = (g * 2 + 1) * 16 + (lane & 7) + (((lane >> 3) & 1) << 3);
        int vseg = (lane >> 4) & 1;
        vfo10 = vrow * 64 + ((vseg)     ^ ((vrow >> 1) & 3)) * 16;
        vfo11 = vrow * 64 + ((vseg + 2) ^ ((vrow >> 1) & 3)) * 16;
    }

    int cur = 0;
    for (int t = 0; t < NTILES; t++) {
        if (t < NTILES - 1) CP_WAIT1(); else CP_WAIT0();
        __syncthreads();

        if (t < NTILES - 2) {
            int nxt2 = cur + 2; if (nxt2 >= 3) nxt2 -= 3;
            int jb2 = (t + 2) * 128;
            cp16(sb + SK_OFF + nxt2 * 4096 + koff, &g_Kh[b][jb2 + kr][ks * 8]);
            cp16(sb + SV_OFF + nxt2 * 8192 + voff0, &g_Vh[b][jb2 + vr0][vs0 * 8]);
            cp16(sb + SV_OFF + nxt2 * 8192 + voff1, &g_Vh[b][jb2 + vr1][vs1 * 8]);
            CP_COMMIT();
        }

        uint32_t kb = sb + SK_OFF + cur * 4096;
        uint32_t vb = sb + SV_OFF + cur * 8192;

        #pragma unroll
        for (int np = 0; np < 2; np++) {
            uint32_t kf[4];
            ldsm4(kf, kb + (np ? kfo1 : kfo0));
            uint32_t vf0[4], vf1[4];
            ldsm4t(vf0, vb + (np ? vfo10 : vfo00));
            ldsm4t(vf1, vb + (np ? vfo11 : vfo01));
            #pragma unroll
            for (int fr = 0; fr < 2; fr++) {
                uint32_t s0[2], s1[2];
                mma16816h(s0, qa[fr], kf[0], kf[1], mch[fr][0], mch[fr][1]);
                mma16816h(s1, qa[fr], kf[2], kf[3], mch[fr][0], mch[fr][1]);

                uint32_t pA[4];
                pA[0] = ex2h(s0[0]);   // == PV A-fragment a0 (rows r,   k 0..7)
                pA[1] = ex2h(s0[1]);   // a1 (rows r+8, k 0..7)
                pA[2] = ex2h(s1[0]);   // a2 (rows r,   k 8..15)
                pA[3] = ex2h(s1[1]);   // a3 (rows r+8, k 8..15)

                mma16816(Dl[fr], pA, ONE2, ONE2);
                mma16816(Dc[fr] + 0,  pA, vf0[0], vf0[1]);
                mma16816(Dc[fr] + 4,  pA, vf0[2], vf0[3]);
                mma16816(Dc[fr] + 8,  pA, vf1[0], vf1[1]);
                mma16816(Dc[fr] + 12, pA, vf1[2], vf1[3]);
            }
        }
        cur++; if (cur == 3) cur = 0;
    }

    // ---- combine the 4 j-groups' partials (scratch overlays K/V region) ----
    __syncthreads();
    float* scr = (float*)sm;
    if (g > 0) {
        float* p = scr + (((g - 1) * 2 + rh) * 32 + lane) * 37;
        #pragma unroll
        for (int fr = 0; fr < 2; fr++) {
            #pragma unroll
            for (int q = 0; q < 16; q++) p[fr * 16 + q] = Dc[fr][q];
        }
        p[32] = Dl[0][0]; p[33] = Dl[0][2];
        p[34] = Dl[1][0]; p[35] = Dl[1][2];
    }
    __syncthreads();

    if (g == 0) {
        float la[2], lb[2];
        la[0] = Dl[0][0]; lb[0] = Dl[0][2];
        la[1] = Dl[1][0]; lb[1] = Dl[1][2];
        #pragma unroll
        for (int gg = 0; gg < 3; gg++) {
            const float* p = scr + ((gg * 2 + rh) * 32 + lane) * 37;
            #pragma unroll
            for (int fr = 0; fr < 2; fr++) {
                #pragma unroll
                for (int q = 0; q < 16; q++) Dc[fr][q] += p[fr * 16 + q];
            }
            la[0] += p[32]; lb[0] += p[33];
            la[1] += p[34]; lb[1] += p[35];
        }

        float gm = gamma[0];
        #pragma unroll
        for (int fr = 0; fr < 2; fr++) {
            float ra = gm / la[fr], rb = gm / lb[fr];
            int ia = i0 + rh * 32 + fr * 16 + (lane >> 2);
            size_t ba = (size_t)b * 262144 + (size_t)ia * 32;
            size_t bb = ba + 8 * 32;
            #pragma unroll
            for (int nt = 0; nt < 4; nt++) {
                int col = nt * 8 + (lane & 3) * 2;
                float2 iv = *(const float2*)(inp + ba + col);
                float2 ov;
                ov.x = Dc[fr][nt * 4 + 0] * ra + iv.x;
                ov.y = Dc[fr][nt * 4 + 1] * ra + iv.y;
                *(float2*)(out + ba + col) = ov;
                iv = *(const float2*)(inp + bb + col);
                ov.x = Dc[fr][nt * 4 + 2] * rb + iv.x;
                ov.y = Dc[fr][nt * 4 + 3] * rb + iv.y;
                *(float2*)(out + bb + col) = ov;
            }
        }
    }
}

extern "C" void kernel_launch(void* const* d_in, const int* in_sizes, int n_in,
                              void* d_out, int out_size) {
    const float* inp   = (const float*)d_in[0];
    const float* W1    = (const float*)d_in[1];
    const float* b1    = (const float*)d_in[2];
    const float* W2    = (const float*)d_in[3];
    const float* b2    = (const float*)d_in[4];
    const float* gamma = (const float*)d_in[5];
    float* out = (float*)d_out;

    fused_kernel<<<dim3(NN / BM, NB), 256>>>(inp, W1, b1, W2, b2, gamma, out);
}